// round 1
// baseline (speedup 1.0000x reference)
#include <cuda_runtime.h>
#include <math.h>

#define BB 4
#define NSEQ 8192
#define DD 512
#define HH 2
#define DH 64
#define INNER 128
#define MM 256
#define LLM 32
#define BH (BB*HH)
#define TOK (BB*NSEQ)
#define KERN 33

// ---------------- static device scratch (no allocation allowed) ----------------
__device__ float g_xn[(size_t)TOK*DD];          // 64MB  layernormed x
__device__ float g_q[(size_t)BH*NSEQ*DH];       // 16MB
__device__ float g_k[(size_t)BH*NSEQ*DH];
__device__ float g_v[(size_t)BH*NSEQ*DH];
__device__ float g_ql[BH*MM*DH];
__device__ float g_kl[BH*MM*DH];
__device__ float g_a2[BH*MM*MM];
__device__ float g_xz[BH*MM*MM];
__device__ float g_t1[BH*MM*MM];
__device__ float g_t2[BH*MM*MM];
__device__ float g_za[BH*MM*MM];
__device__ float g_zb[BH*MM*MM];
__device__ float g_sim[(size_t)BH*MM*NSEQ];     // 64MB  sim3/a3
__device__ float g_a3v[BH*MM*DH];
__device__ float g_w2[BH*MM*DH];
__device__ float g_out1[(size_t)BH*NSEQ*DH];    // 16MB  a1@W2 (+conv)
__device__ float g_part[BH*8*MM*DH];            // split-K partials
__device__ unsigned g_max0, g_max1;

// ---------------- kernels ----------------

__global__ void init_kernel() { g_max0 = 0u; g_max1 = 0u; }

// LayerNorm: one block per token, 128 threads x float4
__global__ __launch_bounds__(128) void ln_kernel(const float* __restrict__ x,
                                                 const float* __restrict__ gamma,
                                                 const float* __restrict__ beta) {
    int t = blockIdx.x, tid = threadIdx.x;
    const float4* xr = (const float4*)(x + (size_t)t * DD);
    float4 v = xr[tid];
    float s  = v.x + v.y + v.z + v.w;
    float sq = v.x*v.x + v.y*v.y + v.z*v.z + v.w*v.w;
    __shared__ float sb[8];
    #pragma unroll
    for (int o = 16; o; o >>= 1) {
        s  += __shfl_xor_sync(0xffffffffu, s, o);
        sq += __shfl_xor_sync(0xffffffffu, sq, o);
    }
    int w = tid >> 5, l = tid & 31;
    if (l == 0) { sb[w] = s; sb[4 + w] = sq; }
    __syncthreads();
    if (tid == 0) {
        sb[0] = sb[0] + sb[1] + sb[2] + sb[3];
        sb[4] = sb[4] + sb[5] + sb[6] + sb[7];
    }
    __syncthreads();
    float mu  = sb[0] * (1.f / DD);
    float var = sb[4] * (1.f / DD) - mu * mu;
    float rs  = rsqrtf(var + 1e-5f);
    float4 g4 = ((const float4*)gamma)[tid];
    float4 b4 = ((const float4*)beta)[tid];
    float4 o;
    o.x = (v.x - mu) * rs * g4.x + b4.x;
    o.y = (v.y - mu) * rs * g4.y + b4.y;
    o.z = (v.z - mu) * rs * g4.z + b4.z;
    o.w = (v.w - mu) * rs * g4.w + b4.w;
    ((float4*)(g_xn + (size_t)t * DD))[tid] = o;
}

// QKV GEMM: xn(32768x512) @ w_qkv(512x384) -> q,k,v in (b,h,n,d) layout; q*0.125
__global__ __launch_bounds__(256) void qkv_kernel(const float* __restrict__ wqkv) {
    __shared__ float As[8][132];
    __shared__ float Bs[8][132];
    int tid = threadIdx.x;
    int row0 = blockIdx.x * 128, col0 = blockIdx.y * 128;
    int aRow = tid >> 1, aK = (tid & 1) * 4;
    int bK = tid >> 5, bCol = (tid & 31) * 4;
    int ty = tid >> 4, tx = tid & 15;
    float acc[8][8];
    #pragma unroll
    for (int i = 0; i < 8; i++)
        #pragma unroll
        for (int j = 0; j < 8; j++) acc[i][j] = 0.f;
    for (int kt = 0; kt < DD; kt += 8) {
        float4 av = *(const float4*)&g_xn[(size_t)(row0 + aRow) * DD + kt + aK];
        As[aK + 0][aRow] = av.x; As[aK + 1][aRow] = av.y;
        As[aK + 2][aRow] = av.z; As[aK + 3][aRow] = av.w;
        float4 bv = *(const float4*)&wqkv[(size_t)(kt + bK) * 384 + col0 + bCol];
        *(float4*)&Bs[bK][bCol] = bv;
        __syncthreads();
        #pragma unroll
        for (int kk = 0; kk < 8; kk++) {
            float a[8], b[8];
            *(float4*)(a)     = *(float4*)&As[kk][ty * 8];
            *(float4*)(a + 4) = *(float4*)&As[kk][ty * 8 + 4];
            *(float4*)(b)     = *(float4*)&Bs[kk][tx * 8];
            *(float4*)(b + 4) = *(float4*)&Bs[kk][tx * 8 + 4];
            #pragma unroll
            for (int i = 0; i < 8; i++)
                #pragma unroll
                for (int j = 0; j < 8; j++) acc[i][j] += a[i] * b[j];
        }
        __syncthreads();
    }
    #pragma unroll
    for (int i = 0; i < 8; i++) {
        int tok = row0 + ty * 8 + i;
        int bb = tok >> 13, n = tok & 8191;
        #pragma unroll
        for (int j = 0; j < 8; j++) {
            int c = col0 + tx * 8 + j;
            int which = c >> 7, hd = c & 127;
            int h = hd >> 6, d = hd & 63;
            size_t dst = (((size_t)(bb * HH + h)) * NSEQ + n) * DH + d;
            float vv = acc[i][j];
            if (which == 0)      g_q[dst] = vv * 0.125f;
            else if (which == 1) g_k[dst] = vv;
            else                 g_v[dst] = vv;
        }
    }
}

// landmark means over 32 consecutive tokens
__global__ void landmark_kernel() {
    int bh = blockIdx.x, m = blockIdx.y, d = threadIdx.x;
    size_t base = ((size_t)bh * NSEQ + m * LLM) * DH + d;
    float sq = 0.f, sk = 0.f;
    #pragma unroll 8
    for (int i = 0; i < LLM; i++) { sq += g_q[base + (size_t)i * DH]; sk += g_k[base + (size_t)i * DH]; }
    g_ql[(bh * MM + m) * DH + d] = sq * (1.f / LLM);
    g_kl[(bh * MM + m) * DH + d] = sk * (1.f / LLM);
}

// sim2 + softmax -> a2 : one block per (bh, row i), thread j = landmark col
__global__ __launch_bounds__(256) void sim2_kernel() {
    int bh = blockIdx.x >> 8, i = blockIdx.x & 255;
    int tid = threadIdx.x;
    __shared__ float qs[DH];
    __shared__ float red[8];
    if (tid < DH) qs[tid] = g_ql[(bh * MM + i) * DH + tid];
    __syncthreads();
    const float* kr = &g_kl[(bh * MM + tid) * DH];
    float s = 0.f;
    #pragma unroll
    for (int d = 0; d < DH; d += 4) {
        float4 kv = *(const float4*)&kr[d];
        s += qs[d] * kv.x + qs[d + 1] * kv.y + qs[d + 2] * kv.z + qs[d + 3] * kv.w;
    }
    // block max
    float m = s;
    #pragma unroll
    for (int o = 16; o; o >>= 1) m = fmaxf(m, __shfl_xor_sync(0xffffffffu, m, o));
    int w = tid >> 5, l = tid & 31;
    if (l == 0) red[w] = m;
    __syncthreads();
    if (w == 0) {
        float t = red[l & 7];
        #pragma unroll
        for (int o = 4; o; o >>= 1) t = fmaxf(t, __shfl_xor_sync(0xffffffffu, t, o));
        if (l == 0) red[0] = t;
    }
    __syncthreads();
    m = red[0];
    __syncthreads();
    float e = __expf(s - m);
    float su = e;
    #pragma unroll
    for (int o = 16; o; o >>= 1) su += __shfl_xor_sync(0xffffffffu, su, o);
    if (l == 0) red[w] = su;
    __syncthreads();
    if (w == 0) {
        float t = red[l & 7];
        #pragma unroll
        for (int o = 4; o; o >>= 1) t += __shfl_xor_sync(0xffffffffu, t, o);
        if (l == 0) red[0] = t;
    }
    __syncthreads();
    g_a2[((size_t)bh * MM + i) * MM + tid] = e / red[0];
}

// global max of abs row-sums (mode0) and abs col-sums (mode1) across ALL matrices
__global__ __launch_bounds__(256) void absmax_kernel() {
    int bh = blockIdx.x, mode = blockIdx.y, tid = threadIdx.x;
    const float* A = &g_a2[(size_t)bh * MM * MM];
    float s = 0.f;
    if (mode == 0) { for (int j = 0; j < MM; j++) s += fabsf(A[tid * MM + j]); }
    else           { for (int i = 0; i < MM; i++) s += fabsf(A[i * MM + tid]); }
    // block max then atomicMax (positive floats: uint-bit compare is monotone)
    float m = s;
    #pragma unroll
    for (int o = 16; o; o >>= 1) m = fmaxf(m, __shfl_xor_sync(0xffffffffu, m, o));
    __shared__ float red[8];
    int w = tid >> 5, l = tid & 31;
    if (l == 0) red[w] = m;
    __syncthreads();
    if (tid == 0) {
        float t = red[0];
        for (int u = 1; u < 8; u++) t = fmaxf(t, red[u]);
        atomicMax(mode == 0 ? &g_max0 : &g_max1, __float_as_uint(t));
    }
}

// z0 = a2^T / (max0*max1)
__global__ __launch_bounds__(256) void zinit_kernel() {
    int bh = blockIdx.x >> 8, i = blockIdx.x & 255, j = threadIdx.x;
    float inv = 1.f / (__uint_as_float(g_max0) * __uint_as_float(g_max1));
    g_za[((size_t)bh * MM + i) * MM + j] = g_a2[((size_t)bh * MM + j) * MM + i] * inv;
}

// batched 256x256x256: C = alpha*(A@B) + beta*A + gamma*I
__global__ __launch_bounds__(256) void bmm_kernel(const float* __restrict__ A,
                                                  const float* __restrict__ Bm,
                                                  float* __restrict__ C,
                                                  float alpha, float beta, float gam) {
    int bh = blockIdx.z;
    size_t base = (size_t)bh * MM * MM;
    __shared__ float As[16][68];
    __shared__ float Bs[16][64];
    int tid = threadIdx.x;
    int i0 = blockIdx.x * 64, j0 = blockIdx.y * 64;
    int aR = tid >> 2, aK = (tid & 3) * 4;
    int bK = tid >> 4, bC = (tid & 15) * 4;
    int ty = tid >> 4, tx = tid & 15;
    float acc[4][4];
    #pragma unroll
    for (int i = 0; i < 4; i++)
        #pragma unroll
        for (int j = 0; j < 4; j++) acc[i][j] = 0.f;
    for (int kt = 0; kt < MM; kt += 16) {
        float4 av = *(const float4*)&A[base + (size_t)(i0 + aR) * MM + kt + aK];
        As[aK + 0][aR] = av.x; As[aK + 1][aR] = av.y;
        As[aK + 2][aR] = av.z; As[aK + 3][aR] = av.w;
        float4 bv = *(const float4*)&Bm[base + (size_t)(kt + bK) * MM + j0 + bC];
        *(float4*)&Bs[bK][bC] = bv;
        __syncthreads();
        #pragma unroll
        for (int kk = 0; kk < 16; kk++) {
            float a[4], b[4];
            *(float4*)a = *(float4*)&As[kk][ty * 4];
            *(float4*)b = *(float4*)&Bs[kk][tx * 4];
            #pragma unroll
            for (int i = 0; i < 4; i++)
                #pragma unroll
                for (int j = 0; j < 4; j++) acc[i][j] += a[i] * b[j];
        }
        __syncthreads();
    }
    #pragma unroll
    for (int ii = 0; ii < 4; ii++) {
        int i = i0 + ty * 4 + ii;
        #pragma unroll
        for (int jj = 0; jj < 4; jj++) {
            int j = j0 + tx * 4 + jj;
            float r = alpha * acc[ii][jj];
            if (beta != 0.f) r += beta * A[base + (size_t)i * MM + j];
            if (i == j) r += gam;
            C[base + (size_t)i * MM + j] = r;
        }
    }
}

// sim3 = q_l @ k^T : (bh, 256, 8192), tiles 64(i) x 128(j), K=64
__global__ __launch_bounds__(256) void sim3_kernel() {
    extern __shared__ float sm[];
    float* Qs = sm;              // [64][68] = 4352
    float* Ks = sm + 4352;       // [64][132] = 8448
    int bh = blockIdx.z;
    int i0 = blockIdx.x * 64, j0 = blockIdx.y * 128;
    int tid = threadIdx.x;
    {
        int r = tid >> 2;
        #pragma unroll
        for (int u = 0; u < 4; u++) {
            int k4 = (tid & 3) * 4 + u * 16;
            float4 v = *(const float4*)&g_ql[((size_t)bh * MM + i0 + r) * DH + k4];
            Qs[(k4 + 0) * 68 + r] = v.x; Qs[(k4 + 1) * 68 + r] = v.y;
            Qs[(k4 + 2) * 68 + r] = v.z; Qs[(k4 + 3) * 68 + r] = v.w;
        }
        int rj = tid >> 1;
        int kb = (tid & 1) * 32;
        #pragma unroll
        for (int u = 0; u < 8; u++) {
            int k4 = kb + u * 4;
            float4 v = *(const float4*)&g_k[((size_t)bh * NSEQ + j0 + rj) * DH + k4];
            Ks[(k4 + 0) * 132 + rj] = v.x; Ks[(k4 + 1) * 132 + rj] = v.y;
            Ks[(k4 + 2) * 132 + rj] = v.z; Ks[(k4 + 3) * 132 + rj] = v.w;
        }
    }
    __syncthreads();
    int ty = tid >> 4, tx = tid & 15;
    float acc[4][8];
    #pragma unroll
    for (int i = 0; i < 4; i++)
        #pragma unroll
        for (int j = 0; j < 8; j++) acc[i][j] = 0.f;
    #pragma unroll 8
    for (int kk = 0; kk < 64; kk++) {
        float a[4], b[8];
        *(float4*)a = *(float4*)&Qs[kk * 68 + ty * 4];
        *(float4*)(b)     = *(float4*)&Ks[kk * 132 + tx * 8];
        *(float4*)(b + 4) = *(float4*)&Ks[kk * 132 + tx * 8 + 4];
        #pragma unroll
        for (int i = 0; i < 4; i++)
            #pragma unroll
            for (int j = 0; j < 8; j++) acc[i][j] += a[i] * b[j];
    }
    #pragma unroll
    for (int ii = 0; ii < 4; ii++) {
        size_t rb = ((size_t)bh * MM + i0 + ty * 4 + ii) * NSEQ + j0 + tx * 8;
        #pragma unroll
        for (int jj = 0; jj < 8; jj++) g_sim[rb + jj] = acc[ii][jj];
    }
}

// softmax over last dim (8192), in place on g_sim
__global__ __launch_bounds__(256) void softmaxN_kernel() {
    __shared__ float buf[NSEQ];
    __shared__ float red[8];
    int tid = threadIdx.x;
    float* row = &g_sim[(size_t)blockIdx.x * NSEQ];
    float4* b4 = (float4*)buf;
    const float4* r4 = (const float4*)row;
    float lm = -1e30f;
    #pragma unroll
    for (int u = 0; u < 8; u++) {
        float4 v = r4[tid + u * 256];
        b4[tid + u * 256] = v;
        lm = fmaxf(lm, fmaxf(fmaxf(v.x, v.y), fmaxf(v.z, v.w)));
    }
    #pragma unroll
    for (int o = 16; o; o >>= 1) lm = fmaxf(lm, __shfl_xor_sync(0xffffffffu, lm, o));
    int w = tid >> 5, l = tid & 31;
    if (l == 0) red[w] = lm;
    __syncthreads();
    if (tid == 0) {
        float t = red[0];
        for (int u = 1; u < 8; u++) t = fmaxf(t, red[u]);
        red[0] = t;
    }
    __syncthreads();
    float m = red[0];
    __syncthreads();
    float ls = 0.f;
    for (int i = tid; i < NSEQ; i += 256) {
        float e = __expf(buf[i] - m);
        buf[i] = e;
        ls += e;
    }
    #pragma unroll
    for (int o = 16; o; o >>= 1) ls += __shfl_xor_sync(0xffffffffu, ls, o);
    if (l == 0) red[w] = ls;
    __syncthreads();
    if (tid == 0) {
        float t = 0.f;
        for (int u = 0; u < 8; u++) t += red[u];
        red[0] = 1.f / t;
    }
    __syncthreads();
    float inv = red[0];
    float4* o4 = (float4*)row;
    #pragma unroll
    for (int u = 0; u < 8; u++) {
        float4 v = b4[tid + u * 256];
        v.x *= inv; v.y *= inv; v.z *= inv; v.w *= inv;
        o4[tid + u * 256] = v;
    }
}

// a3 @ v split-K partials: grid (4 itiles, 8 ksplits, BH), each 64x64 tile
__global__ __launch_bounds__(256) void a3vpart_kernel() {
    __shared__ float As[16][68];
    __shared__ float Bs[16][64];
    int bh = blockIdx.z, ks = blockIdx.y;
    int i0 = blockIdx.x * 64;
    int tid = threadIdx.x;
    int aR = tid >> 2, aK = (tid & 3) * 4;
    int bK = tid >> 4, bC = (tid & 15) * 4;
    int ty = tid >> 4, tx = tid & 15;
    float acc[4][4];
    #pragma unroll
    for (int i = 0; i < 4; i++)
        #pragma unroll
        for (int j = 0; j < 4; j++) acc[i][j] = 0.f;
    int kbeg = ks * 1024, kend = kbeg + 1024;
    for (int kt = kbeg; kt < kend; kt += 16) {
        float4 av = *(const float4*)&g_sim[((size_t)bh * MM + i0 + aR) * NSEQ + kt + aK];
        As[aK + 0][aR] = av.x; As[aK + 1][aR] = av.y;
        As[aK + 2][aR] = av.z; As[aK + 3][aR] = av.w;
        float4 bv = *(const float4*)&g_v[((size_t)bh * NSEQ + kt + bK) * DH + bC];
        *(float4*)&Bs[bK][bC] = bv;
        __syncthreads();
        #pragma unroll
        for (int kk = 0; kk < 16; kk++) {
            float a[4], b[4];
            *(float4*)a = *(float4*)&As[kk][ty * 4];
            *(float4*)b = *(float4*)&Bs[kk][tx * 4];
            #pragma unroll
            for (int i = 0; i < 4; i++)
                #pragma unroll
                for (int j = 0; j < 4; j++) acc[i][j] += a[i] * b[j];
        }
        __syncthreads();
    }
    #pragma unroll
    for (int ii = 0; ii < 4; ii++)
        #pragma unroll
        for (int jj = 0; jj < 4; jj++)
            g_part[(((size_t)bh * 8 + ks) * MM + i0 + ty * 4 + ii) * DH + tx * 4 + jj] = acc[ii][jj];
}

__global__ void a3vred_kernel() {
    int e = blockIdx.x * 256 + threadIdx.x;
    int bh = e >> 14, r = e & 16383;
    float s = 0.f;
    #pragma unroll
    for (int ks = 0; ks < 8; ks++) s += g_part[((size_t)bh * 8 + ks) * 16384 + r];
    g_a3v[e] = s;
}

// W2 = Z @ a3v : (256x256)@(256x64)
__global__ __launch_bounds__(256) void w2_kernel(const float* __restrict__ Z) {
    __shared__ float As[16][68];
    __shared__ float Bs[16][64];
    int bh = blockIdx.y;
    int i0 = blockIdx.x * 64;
    int tid = threadIdx.x;
    int aR = tid >> 2, aK = (tid & 3) * 4;
    int bK = tid >> 4, bC = (tid & 15) * 4;
    int ty = tid >> 4, tx = tid & 15;
    float acc[4][4];
    #pragma unroll
    for (int i = 0; i < 4; i++)
        #pragma unroll
        for (int j = 0; j < 4; j++) acc[i][j] = 0.f;
    for (int kt = 0; kt < MM; kt += 16) {
        float4 av = *(const float4*)&Z[((size_t)bh * MM + i0 + aR) * MM + kt + aK];
        As[aK + 0][aR] = av.x; As[aK + 1][aR] = av.y;
        As[aK + 2][aR] = av.z; As[aK + 3][aR] = av.w;
        float4 bv = *(const float4*)&g_a3v[((size_t)bh * MM + kt + bK) * DH + bC];
        *(float4*)&Bs[bK][bC] = bv;
        __syncthreads();
        #pragma unroll
        for (int kk = 0; kk < 16; kk++) {
            float a[4], b[4];
            *(float4*)a = *(float4*)&As[kk][ty * 4];
            *(float4*)b = *(float4*)&Bs[kk][tx * 4];
            #pragma unroll
            for (int i = 0; i < 4; i++)
                #pragma unroll
                for (int j = 0; j < 4; j++) acc[i][j] += a[i] * b[j];
        }
        __syncthreads();
    }
    #pragma unroll
    for (int ii = 0; ii < 4; ii++)
        #pragma unroll
        for (int jj = 0; jj < 4; jj++)
            g_w2[((size_t)bh * MM + i0 + ty * 4 + ii) * DH + tx * 4 + jj] = acc[ii][jj];
}

// fused: out1 = softmax(q @ k_l^T) @ W2, 32 q-rows per block
__global__ __launch_bounds__(256) void a1out_kernel() {
    extern __shared__ float sm[];
    float* kls = sm;                    // 256*64
    float* w2s = sm + 16384;            // 256*64
    float* qs  = sm + 32768;            // 32*65
    float* sc  = sm + 32768 + 2080;     // 32*257
    __shared__ float pm[256];
    __shared__ float rmax[32], rinv[32];
    int bh = blockIdx.y;
    int n0 = blockIdx.x * 32;
    int tid = threadIdx.x;
    {
        const float4* klg = (const float4*)&g_kl[(size_t)bh * MM * DH];
        const float4* wg  = (const float4*)&g_w2[(size_t)bh * MM * DH];
        float4* kl4 = (float4*)kls;
        float4* w4  = (float4*)w2s;
        #pragma unroll
        for (int u = 0; u < 16; u++) {
            kl4[tid + u * 256] = klg[tid + u * 256];
            w4[tid + u * 256]  = wg[tid + u * 256];
        }
        #pragma unroll
        for (int u = 0; u < 8; u++) {
            int e = tid + u * 256;
            int r = e >> 6, d = e & 63;
            qs[r * 65 + d] = g_q[((size_t)bh * NSEQ + n0 + r) * DH + d];
        }
    }
    __syncthreads();
    int r = tid & 31, g = tid >> 5, j0 = g * 32;
    float sacc[32];
    #pragma unroll
    for (int jj = 0; jj < 32; jj++) sacc[jj] = 0.f;
    for (int d = 0; d < DH; d++) {
        float qv = qs[r * 65 + d];
        #pragma unroll
        for (int jj = 0; jj < 32; jj++) sacc[jj] += qv * kls[(j0 + jj) * 64 + d];
    }
    float lm = -1e30f;
    #pragma unroll
    for (int jj = 0; jj < 32; jj++) lm = fmaxf(lm, sacc[jj]);
    pm[tid] = lm;
    __syncthreads();
    if (tid < 32) {
        float m = pm[tid];
        #pragma unroll
        for (int gg = 1; gg < 8; gg++) m = fmaxf(m, pm[gg * 32 + tid]);
        rmax[tid] = m;
    }
    __syncthreads();
    float m = rmax[r];
    float ls = 0.f;
    #pragma unroll
    for (int jj = 0; jj < 32; jj++) {
        float e = __expf(sacc[jj] - m);
        sc[r * 257 + j0 + jj] = e;
        ls += e;
    }
    pm[tid] = ls;
    __syncthreads();
    if (tid < 32) {
        float s2 = 0.f;
        #pragma unroll
        for (int gg = 0; gg < 8; gg++) s2 += pm[gg * 32 + tid];
        rinv[tid] = 1.f / s2;
    }
    __syncthreads();
    int ro = tid >> 3, dg = tid & 7;
    float acc[8];
    #pragma unroll
    for (int dd = 0; dd < 8; dd++) acc[dd] = 0.f;
    for (int j = 0; j < MM; j++) {
        float p = sc[ro * 257 + j];
        const float* wrow = &w2s[j * 64 + dg * 8];
        #pragma unroll
        for (int dd = 0; dd < 8; dd++) acc[dd] += p * wrow[dd];
    }
    float inv = rinv[ro];
    size_t ob = ((size_t)bh * NSEQ + n0 + ro) * DH + dg * 8;
    #pragma unroll
    for (int dd = 0; dd < 8; dd++) g_out1[ob + dd] = acc[dd] * inv;
}

// depthwise conv over sequence (kernel 33, same pad), out1 += conv(v)
__global__ __launch_bounds__(256) void conv_kernel(const float* __restrict__ wres) {
    __shared__ float sv[160 * 64];
    __shared__ float wl[KERN];
    int bh = blockIdx.y, h = bh & 1;
    int n0 = blockIdx.x * 128;
    int tid = threadIdx.x;
    if (tid < KERN) wl[tid] = wres[h * KERN + tid];
    #pragma unroll
    for (int u = 0; u < 10; u++) {
        int e4 = tid + u * 256;
        int li = e4 >> 4, d4 = (e4 & 15) * 4;
        int n = n0 - 16 + li;
        float4 val = make_float4(0.f, 0.f, 0.f, 0.f);
        if (n >= 0 && n < NSEQ) val = *(const float4*)&g_v[((size_t)bh * NSEQ + n) * DH + d4];
        *(float4*)&sv[li * 64 + d4] = val;
    }
    __syncthreads();
    int d = tid & 63, rg = tid >> 6;
    for (int i = 0; i < 32; i++) {
        int rl = rg * 32 + i;
        float s = 0.f;
        #pragma unroll
        for (int t = 0; t < KERN; t++) s += wl[t] * sv[(rl + t) * 64 + d];
        g_out1[((size_t)bh * NSEQ + n0 + rl) * DH + d] += s;
    }
}

// final: out = x + (gather(out1) @ w_out + b_out)
__global__ __launch_bounds__(256) void outgemm_kernel(const float* __restrict__ x,
                                                      const float* __restrict__ wout,
                                                      const float* __restrict__ bout,
                                                      float* __restrict__ out) {
    __shared__ float As[8][132];
    __shared__ float Bs[8][132];
    int tid = threadIdx.x;
    int row0 = blockIdx.x * 128, col0 = blockIdx.y * 128;
    int aRow = tid >> 1, aK = (tid & 1) * 4;
    int bK = tid >> 5, bCol = (tid & 31) * 4;
    int ty = tid >> 4, tx = tid & 15;
    int tokA = row0 + aRow;
    int bbA = tokA >> 13, nA = tokA & 8191;
    float acc[8][8];
    #pragma unroll
    for (int i = 0; i < 8; i++)
        #pragma unroll
        for (int j = 0; j < 8; j++) acc[i][j] = 0.f;
    for (int kt = 0; kt < INNER; kt += 8) {
        int c = kt + aK;
        int h = c >> 6, d = c & 63;
        float4 av = *(const float4*)&g_out1[(((size_t)(bbA * HH + h)) * NSEQ + nA) * DH + d];
        As[aK + 0][aRow] = av.x; As[aK + 1][aRow] = av.y;
        As[aK + 2][aRow] = av.z; As[aK + 3][aRow] = av.w;
        float4 bv = *(const float4*)&wout[(size_t)(kt + bK) * DD + col0 + bCol];
        *(float4*)&Bs[bK][bCol] = bv;
        __syncthreads();
        #pragma unroll
        for (int kk = 0; kk < 8; kk++) {
            float a[8], b[8];
            *(float4*)(a)     = *(float4*)&As[kk][ty * 8];
            *(float4*)(a + 4) = *(float4*)&As[kk][ty * 8 + 4];
            *(float4*)(b)     = *(float4*)&Bs[kk][tx * 8];
            *(float4*)(b + 4) = *(float4*)&Bs[kk][tx * 8 + 4];
            #pragma unroll
            for (int i = 0; i < 8; i++)
                #pragma unroll
                for (int j = 0; j < 8; j++) acc[i][j] += a[i] * b[j];
        }
        __syncthreads();
    }
    #pragma unroll
    for (int i = 0; i < 8; i++) {
        int tok = row0 + ty * 8 + i;
        #pragma unroll
        for (int j = 0; j < 8; j++) {
            int c = col0 + tx * 8 + j;
            out[(size_t)tok * DD + c] = acc[i][j] + bout[c] + x[(size_t)tok * DD + c];
        }
    }
}

// ---------------- launch ----------------
extern "C" void kernel_launch(void* const* d_in, const int* in_sizes, int n_in,
                              void* d_out, int out_size) {
    const float* x     = (const float*)d_in[0];
    const float* gamma = (const float*)d_in[1];
    const float* beta  = (const float*)d_in[2];
    const float* wqkv  = (const float*)d_in[3];
    const float* wout  = (const float*)d_in[4];
    const float* bout  = (const float*)d_in[5];
    const float* wres  = (const float*)d_in[6];
    float* out = (float*)d_out;

    float *pA2, *pXZ, *pT1, *pT2, *pZA, *pZB;
    cudaGetSymbolAddress((void**)&pA2, g_a2);
    cudaGetSymbolAddress((void**)&pXZ, g_xz);
    cudaGetSymbolAddress((void**)&pT1, g_t1);
    cudaGetSymbolAddress((void**)&pT2, g_t2);
    cudaGetSymbolAddress((void**)&pZA, g_za);
    cudaGetSymbolAddress((void**)&pZB, g_zb);

    cudaFuncSetAttribute(sim3_kernel, cudaFuncAttributeMaxDynamicSharedMemorySize, 51200);
    cudaFuncSetAttribute(a1out_kernel, cudaFuncAttributeMaxDynamicSharedMemorySize, 172288);

    init_kernel<<<1, 1>>>();
    ln_kernel<<<TOK, 128>>>(x, gamma, beta);
    qkv_kernel<<<dim3(TOK / 128, 3), 256>>>(wqkv);
    landmark_kernel<<<dim3(BH, MM), 64>>>();
    sim2_kernel<<<BH * MM, 256>>>();
    absmax_kernel<<<dim3(BH, 2), 256>>>();
    zinit_kernel<<<BH * MM, 256>>>();

    float* zc = pZA;
    float* zn = pZB;
    for (int it = 0; it < 6; it++) {
        bmm_kernel<<<dim3(4, 4, BH), 256>>>(pA2, zc, pXZ, 1.f, 0.f, 0.f);
        bmm_kernel<<<dim3(4, 4, BH), 256>>>(pXZ, pXZ, pT1, 1.f, -7.f, 15.f);
        bmm_kernel<<<dim3(4, 4, BH), 256>>>(pXZ, pT1, pT2, -1.f, 0.f, 13.f);
        bmm_kernel<<<dim3(4, 4, BH), 256>>>(zc, pT2, zn, 0.25f, 0.f, 0.f);
        float* t = zc; zc = zn; zn = t;
    }

    sim3_kernel<<<dim3(4, 64, BH), 256, 51200>>>();
    softmaxN_kernel<<<BH * MM, 256>>>();
    a3vpart_kernel<<<dim3(4, 8, BH), 256>>>();
    a3vred_kernel<<<512, 256>>>();
    w2_kernel<<<dim3(4, BH), 256>>>(zc);
    a1out_kernel<<<dim3(NSEQ / 32, BH), 256, 172288>>>();
    conv_kernel<<<dim3(NSEQ / 128, BH), 256>>>(wres);
    outgemm_kernel<<<dim3(TOK / 128, 4), 256>>>(x, wout, bout, out);
}

// round 2
// speedup vs baseline: 1.0009x; 1.0009x over previous
#include <cuda_runtime.h>
#include <math.h>

#define BB 4
#define NSEQ 8192
#define DD 512
#define HH 2
#define DH 64
#define INNER 128
#define MM 256
#define LLM 32
#define BH (BB*HH)
#define TOK (BB*NSEQ)
#define KERN 33

// ---------------- static device scratch (no allocation allowed) ----------------
__device__ float g_xn[(size_t)TOK*DD];          // 64MB  layernormed x
__device__ float g_q[(size_t)BH*NSEQ*DH];       // 16MB
__device__ float g_k[(size_t)BH*NSEQ*DH];
__device__ float g_v[(size_t)BH*NSEQ*DH];
__device__ float g_ql[BH*MM*DH];
__device__ float g_kl[BH*MM*DH];
__device__ float g_a2[BH*MM*MM];
__device__ float g_xz[BH*MM*MM];
__device__ float g_t1[BH*MM*MM];
__device__ float g_t2[BH*MM*MM];
__device__ float g_za[BH*MM*MM];
__device__ float g_zb[BH*MM*MM];
__device__ float g_sim[(size_t)BH*MM*NSEQ];     // 64MB  sim3/a3
__device__ float g_a3v[BH*MM*DH];
__device__ float g_w2[BH*MM*DH];
__device__ float g_out1[(size_t)BH*NSEQ*DH];    // 16MB  a1@W2 (+conv)
__device__ float g_part[BH*8*MM*DH];            // split-K partials
__device__ unsigned g_max0, g_max1;

// ---------------- kernels ----------------

__global__ void init_kernel() { g_max0 = 0u; g_max1 = 0u; }

// LayerNorm: one block per token, 128 threads x float4
__global__ __launch_bounds__(128) void ln_kernel(const float* __restrict__ x,
                                                 const float* __restrict__ gamma,
                                                 const float* __restrict__ beta) {
    int t = blockIdx.x, tid = threadIdx.x;
    const float4* xr = (const float4*)(x + (size_t)t * DD);
    float4 v = xr[tid];
    float s  = v.x + v.y + v.z + v.w;
    float sq = v.x*v.x + v.y*v.y + v.z*v.z + v.w*v.w;
    __shared__ float sb[8];
    #pragma unroll
    for (int o = 16; o; o >>= 1) {
        s  += __shfl_xor_sync(0xffffffffu, s, o);
        sq += __shfl_xor_sync(0xffffffffu, sq, o);
    }
    int w = tid >> 5, l = tid & 31;
    if (l == 0) { sb[w] = s; sb[4 + w] = sq; }
    __syncthreads();
    if (tid == 0) {
        sb[0] = sb[0] + sb[1] + sb[2] + sb[3];
        sb[4] = sb[4] + sb[5] + sb[6] + sb[7];
    }
    __syncthreads();
    float mu  = sb[0] * (1.f / DD);
    float var = sb[4] * (1.f / DD) - mu * mu;
    float rs  = rsqrtf(var + 1e-5f);
    float4 g4 = ((const float4*)gamma)[tid];
    float4 b4 = ((const float4*)beta)[tid];
    float4 o;
    o.x = (v.x - mu) * rs * g4.x + b4.x;
    o.y = (v.y - mu) * rs * g4.y + b4.y;
    o.z = (v.z - mu) * rs * g4.z + b4.z;
    o.w = (v.w - mu) * rs * g4.w + b4.w;
    ((float4*)(g_xn + (size_t)t * DD))[tid] = o;
}

// QKV GEMM: xn(32768x512) @ w_qkv(512x384) -> q,k,v in (b,h,n,d) layout; q*0.125
__global__ __launch_bounds__(256) void qkv_kernel(const float* __restrict__ wqkv) {
    __shared__ float As[8][132];
    __shared__ float Bs[8][132];
    int tid = threadIdx.x;
    int row0 = blockIdx.x * 128, col0 = blockIdx.y * 128;
    int aRow = tid >> 1, aK = (tid & 1) * 4;
    int bK = tid >> 5, bCol = (tid & 31) * 4;
    int ty = tid >> 4, tx = tid & 15;
    float acc[8][8];
    #pragma unroll
    for (int i = 0; i < 8; i++)
        #pragma unroll
        for (int j = 0; j < 8; j++) acc[i][j] = 0.f;
    for (int kt = 0; kt < DD; kt += 8) {
        float4 av = *(const float4*)&g_xn[(size_t)(row0 + aRow) * DD + kt + aK];
        As[aK + 0][aRow] = av.x; As[aK + 1][aRow] = av.y;
        As[aK + 2][aRow] = av.z; As[aK + 3][aRow] = av.w;
        float4 bv = *(const float4*)&wqkv[(size_t)(kt + bK) * 384 + col0 + bCol];
        *(float4*)&Bs[bK][bCol] = bv;
        __syncthreads();
        #pragma unroll
        for (int kk = 0; kk < 8; kk++) {
            float a[8], b[8];
            *(float4*)(a)     = *(float4*)&As[kk][ty * 8];
            *(float4*)(a + 4) = *(float4*)&As[kk][ty * 8 + 4];
            *(float4*)(b)     = *(float4*)&Bs[kk][tx * 8];
            *(float4*)(b + 4) = *(float4*)&Bs[kk][tx * 8 + 4];
            #pragma unroll
            for (int i = 0; i < 8; i++)
                #pragma unroll
                for (int j = 0; j < 8; j++) acc[i][j] += a[i] * b[j];
        }
        __syncthreads();
    }
    #pragma unroll
    for (int i = 0; i < 8; i++) {
        int tok = row0 + ty * 8 + i;
        int bb = tok >> 13, n = tok & 8191;
        #pragma unroll
        for (int j = 0; j < 8; j++) {
            int c = col0 + tx * 8 + j;
            int which = c >> 7, hd = c & 127;
            int h = hd >> 6, d = hd & 63;
            size_t dst = (((size_t)(bb * HH + h)) * NSEQ + n) * DH + d;
            float vv = acc[i][j];
            if (which == 0)      g_q[dst] = vv * 0.125f;
            else if (which == 1) g_k[dst] = vv;
            else                 g_v[dst] = vv;
        }
    }
}

// landmark means over 32 consecutive tokens
__global__ void landmark_kernel() {
    int bh = blockIdx.x, m = blockIdx.y, d = threadIdx.x;
    size_t base = ((size_t)bh * NSEQ + m * LLM) * DH + d;
    float sq = 0.f, sk = 0.f;
    #pragma unroll 8
    for (int i = 0; i < LLM; i++) { sq += g_q[base + (size_t)i * DH]; sk += g_k[base + (size_t)i * DH]; }
    g_ql[(bh * MM + m) * DH + d] = sq * (1.f / LLM);
    g_kl[(bh * MM + m) * DH + d] = sk * (1.f / LLM);
}

// sim2 + softmax -> a2 : one block per (bh, row i), thread j = landmark col
__global__ __launch_bounds__(256) void sim2_kernel() {
    int bh = blockIdx.x >> 8, i = blockIdx.x & 255;
    int tid = threadIdx.x;
    __shared__ float qs[DH];
    __shared__ float red[8];
    if (tid < DH) qs[tid] = g_ql[(bh * MM + i) * DH + tid];
    __syncthreads();
    const float* kr = &g_kl[(bh * MM + tid) * DH];
    float s = 0.f;
    #pragma unroll
    for (int d = 0; d < DH; d += 4) {
        float4 kv = *(const float4*)&kr[d];
        s += qs[d] * kv.x + qs[d + 1] * kv.y + qs[d + 2] * kv.z + qs[d + 3] * kv.w;
    }
    // block max
    float m = s;
    #pragma unroll
    for (int o = 16; o; o >>= 1) m = fmaxf(m, __shfl_xor_sync(0xffffffffu, m, o));
    int w = tid >> 5, l = tid & 31;
    if (l == 0) red[w] = m;
    __syncthreads();
    if (w == 0) {
        float t = red[l & 7];
        #pragma unroll
        for (int o = 4; o; o >>= 1) t = fmaxf(t, __shfl_xor_sync(0xffffffffu, t, o));
        if (l == 0) red[0] = t;
    }
    __syncthreads();
    m = red[0];
    __syncthreads();
    float e = __expf(s - m);
    float su = e;
    #pragma unroll
    for (int o = 16; o; o >>= 1) su += __shfl_xor_sync(0xffffffffu, su, o);
    if (l == 0) red[w] = su;
    __syncthreads();
    if (w == 0) {
        float t = red[l & 7];
        #pragma unroll
        for (int o = 4; o; o >>= 1) t += __shfl_xor_sync(0xffffffffu, t, o);
        if (l == 0) red[0] = t;
    }
    __syncthreads();
    g_a2[((size_t)bh * MM + i) * MM + tid] = e / red[0];
}

// global max of abs row-sums (mode0) and abs col-sums (mode1) across ALL matrices
__global__ __launch_bounds__(256) void absmax_kernel() {
    int bh = blockIdx.x, mode = blockIdx.y, tid = threadIdx.x;
    const float* A = &g_a2[(size_t)bh * MM * MM];
    float s = 0.f;
    if (mode == 0) { for (int j = 0; j < MM; j++) s += fabsf(A[tid * MM + j]); }
    else           { for (int i = 0; i < MM; i++) s += fabsf(A[i * MM + tid]); }
    // block max then atomicMax (positive floats: uint-bit compare is monotone)
    float m = s;
    #pragma unroll
    for (int o = 16; o; o >>= 1) m = fmaxf(m, __shfl_xor_sync(0xffffffffu, m, o));
    __shared__ float red[8];
    int w = tid >> 5, l = tid & 31;
    if (l == 0) red[w] = m;
    __syncthreads();
    if (tid == 0) {
        float t = red[0];
        for (int u = 1; u < 8; u++) t = fmaxf(t, red[u]);
        atomicMax(mode == 0 ? &g_max0 : &g_max1, __float_as_uint(t));
    }
}

// z0 = a2^T / (max0*max1)
__global__ __launch_bounds__(256) void zinit_kernel() {
    int bh = blockIdx.x >> 8, i = blockIdx.x & 255, j = threadIdx.x;
    float inv = 1.f / (__uint_as_float(g_max0) * __uint_as_float(g_max1));
    g_za[((size_t)bh * MM + i) * MM + j] = g_a2[((size_t)bh * MM + j) * MM + i] * inv;
}

// batched 256x256x256: C = alpha*(A@B) + beta*A + gamma*I
__global__ __launch_bounds__(256) void bmm_kernel(const float* __restrict__ A,
                                                  const float* __restrict__ Bm,
                                                  float* __restrict__ C,
                                                  float alpha, float beta, float gam) {
    int bh = blockIdx.z;
    size_t base = (size_t)bh * MM * MM;
    __shared__ float As[16][68];
    __shared__ float Bs[16][64];
    int tid = threadIdx.x;
    int i0 = blockIdx.x * 64, j0 = blockIdx.y * 64;
    int aR = tid >> 2, aK = (tid & 3) * 4;
    int bK = tid >> 4, bC = (tid & 15) * 4;
    int ty = tid >> 4, tx = tid & 15;
    float acc[4][4];
    #pragma unroll
    for (int i = 0; i < 4; i++)
        #pragma unroll
        for (int j = 0; j < 4; j++) acc[i][j] = 0.f;
    for (int kt = 0; kt < MM; kt += 16) {
        float4 av = *(const float4*)&A[base + (size_t)(i0 + aR) * MM + kt + aK];
        As[aK + 0][aR] = av.x; As[aK + 1][aR] = av.y;
        As[aK + 2][aR] = av.z; As[aK + 3][aR] = av.w;
        float4 bv = *(const float4*)&Bm[base + (size_t)(kt + bK) * MM + j0 + bC];
        *(float4*)&Bs[bK][bC] = bv;
        __syncthreads();
        #pragma unroll
        for (int kk = 0; kk < 16; kk++) {
            float a[4], b[4];
            *(float4*)a = *(float4*)&As[kk][ty * 4];
            *(float4*)b = *(float4*)&Bs[kk][tx * 4];
            #pragma unroll
            for (int i = 0; i < 4; i++)
                #pragma unroll
                for (int j = 0; j < 4; j++) acc[i][j] += a[i] * b[j];
        }
        __syncthreads();
    }
    #pragma unroll
    for (int ii = 0; ii < 4; ii++) {
        int i = i0 + ty * 4 + ii;
        #pragma unroll
        for (int jj = 0; jj < 4; jj++) {
            int j = j0 + tx * 4 + jj;
            float r = alpha * acc[ii][jj];
            if (beta != 0.f) r += beta * A[base + (size_t)i * MM + j];
            if (i == j) r += gam;
            C[base + (size_t)i * MM + j] = r;
        }
    }
}

// sim3 = q_l @ k^T : (bh, 256, 8192), tiles 64(i) x 128(j), K=64
__global__ __launch_bounds__(256) void sim3_kernel() {
    extern __shared__ float sm[];
    float* Qs = sm;              // [64][68] = 4352
    float* Ks = sm + 4352;       // [64][132] = 8448
    int bh = blockIdx.z;
    int i0 = blockIdx.x * 64, j0 = blockIdx.y * 128;
    int tid = threadIdx.x;
    {
        int r = tid >> 2;
        #pragma unroll
        for (int u = 0; u < 4; u++) {
            int k4 = (tid & 3) * 4 + u * 16;
            float4 v = *(const float4*)&g_ql[((size_t)bh * MM + i0 + r) * DH + k4];
            Qs[(k4 + 0) * 68 + r] = v.x; Qs[(k4 + 1) * 68 + r] = v.y;
            Qs[(k4 + 2) * 68 + r] = v.z; Qs[(k4 + 3) * 68 + r] = v.w;
        }
        int rj = tid >> 1;
        int kb = (tid & 1) * 32;
        #pragma unroll
        for (int u = 0; u < 8; u++) {
            int k4 = kb + u * 4;
            float4 v = *(const float4*)&g_k[((size_t)bh * NSEQ + j0 + rj) * DH + k4];
            Ks[(k4 + 0) * 132 + rj] = v.x; Ks[(k4 + 1) * 132 + rj] = v.y;
            Ks[(k4 + 2) * 132 + rj] = v.z; Ks[(k4 + 3) * 132 + rj] = v.w;
        }
    }
    __syncthreads();
    int ty = tid >> 4, tx = tid & 15;
    float acc[4][8];
    #pragma unroll
    for (int i = 0; i < 4; i++)
        #pragma unroll
        for (int j = 0; j < 8; j++) acc[i][j] = 0.f;
    #pragma unroll 8
    for (int kk = 0; kk < 64; kk++) {
        float a[4], b[8];
        *(float4*)a = *(float4*)&Qs[kk * 68 + ty * 4];
        *(float4*)(b)     = *(float4*)&Ks[kk * 132 + tx * 8];
        *(float4*)(b + 4) = *(float4*)&Ks[kk * 132 + tx * 8 + 4];
        #pragma unroll
        for (int i = 0; i < 4; i++)
            #pragma unroll
            for (int j = 0; j < 8; j++) acc[i][j] += a[i] * b[j];
    }
    #pragma unroll
    for (int ii = 0; ii < 4; ii++) {
        size_t rb = ((size_t)bh * MM + i0 + ty * 4 + ii) * NSEQ + j0 + tx * 8;
        #pragma unroll
        for (int jj = 0; jj < 8; jj++) g_sim[rb + jj] = acc[ii][jj];
    }
}

// softmax over last dim (8192), in place on g_sim
__global__ __launch_bounds__(256) void softmaxN_kernel() {
    __shared__ float buf[NSEQ];
    __shared__ float red[8];
    int tid = threadIdx.x;
    float* row = &g_sim[(size_t)blockIdx.x * NSEQ];
    float4* b4 = (float4*)buf;
    const float4* r4 = (const float4*)row;
    float lm = -1e30f;
    #pragma unroll
    for (int u = 0; u < 8; u++) {
        float4 v = r4[tid + u * 256];
        b4[tid + u * 256] = v;
        lm = fmaxf(lm, fmaxf(fmaxf(v.x, v.y), fmaxf(v.z, v.w)));
    }
    #pragma unroll
    for (int o = 16; o; o >>= 1) lm = fmaxf(lm, __shfl_xor_sync(0xffffffffu, lm, o));
    int w = tid >> 5, l = tid & 31;
    if (l == 0) red[w] = lm;
    __syncthreads();
    if (tid == 0) {
        float t = red[0];
        for (int u = 1; u < 8; u++) t = fmaxf(t, red[u]);
        red[0] = t;
    }
    __syncthreads();
    float m = red[0];
    __syncthreads();
    float ls = 0.f;
    for (int i = tid; i < NSEQ; i += 256) {
        float e = __expf(buf[i] - m);
        buf[i] = e;
        ls += e;
    }
    #pragma unroll
    for (int o = 16; o; o >>= 1) ls += __shfl_xor_sync(0xffffffffu, ls, o);
    if (l == 0) red[w] = ls;
    __syncthreads();
    if (tid == 0) {
        float t = 0.f;
        for (int u = 0; u < 8; u++) t += red[u];
        red[0] = 1.f / t;
    }
    __syncthreads();
    float inv = red[0];
    float4* o4 = (float4*)row;
    #pragma unroll
    for (int u = 0; u < 8; u++) {
        float4 v = b4[tid + u * 256];
        v.x *= inv; v.y *= inv; v.z *= inv; v.w *= inv;
        o4[tid + u * 256] = v;
    }
}

// a3 @ v split-K partials: grid (4 itiles, 8 ksplits, BH), each 64x64 tile
__global__ __launch_bounds__(256) void a3vpart_kernel() {
    __shared__ float As[16][68];
    __shared__ float Bs[16][64];
    int bh = blockIdx.z, ks = blockIdx.y;
    int i0 = blockIdx.x * 64;
    int tid = threadIdx.x;
    int aR = tid >> 2, aK = (tid & 3) * 4;
    int bK = tid >> 4, bC = (tid & 15) * 4;
    int ty = tid >> 4, tx = tid & 15;
    float acc[4][4];
    #pragma unroll
    for (int i = 0; i < 4; i++)
        #pragma unroll
        for (int j = 0; j < 4; j++) acc[i][j] = 0.f;
    int kbeg = ks * 1024, kend = kbeg + 1024;
    for (int kt = kbeg; kt < kend; kt += 16) {
        float4 av = *(const float4*)&g_sim[((size_t)bh * MM + i0 + aR) * NSEQ + kt + aK];
        As[aK + 0][aR] = av.x; As[aK + 1][aR] = av.y;
        As[aK + 2][aR] = av.z; As[aK + 3][aR] = av.w;
        float4 bv = *(const float4*)&g_v[((size_t)bh * NSEQ + kt + bK) * DH + bC];
        *(float4*)&Bs[bK][bC] = bv;
        __syncthreads();
        #pragma unroll
        for (int kk = 0; kk < 16; kk++) {
            float a[4], b[4];
            *(float4*)a = *(float4*)&As[kk][ty * 4];
            *(float4*)b = *(float4*)&Bs[kk][tx * 4];
            #pragma unroll
            for (int i = 0; i < 4; i++)
                #pragma unroll
                for (int j = 0; j < 4; j++) acc[i][j] += a[i] * b[j];
        }
        __syncthreads();
    }
    #pragma unroll
    for (int ii = 0; ii < 4; ii++)
        #pragma unroll
        for (int jj = 0; jj < 4; jj++)
            g_part[(((size_t)bh * 8 + ks) * MM + i0 + ty * 4 + ii) * DH + tx * 4 + jj] = acc[ii][jj];
}

__global__ void a3vred_kernel() {
    int e = blockIdx.x * 256 + threadIdx.x;
    int bh = e >> 14, r = e & 16383;
    float s = 0.f;
    #pragma unroll
    for (int ks = 0; ks < 8; ks++) s += g_part[((size_t)bh * 8 + ks) * 16384 + r];
    g_a3v[e] = s;
}

// W2 = Z @ a3v : (256x256)@(256x64)
__global__ __launch_bounds__(256) void w2_kernel(const float* __restrict__ Z) {
    __shared__ float As[16][68];
    __shared__ float Bs[16][64];
    int bh = blockIdx.y;
    int i0 = blockIdx.x * 64;
    int tid = threadIdx.x;
    int aR = tid >> 2, aK = (tid & 3) * 4;
    int bK = tid >> 4, bC = (tid & 15) * 4;
    int ty = tid >> 4, tx = tid & 15;
    float acc[4][4];
    #pragma unroll
    for (int i = 0; i < 4; i++)
        #pragma unroll
        for (int j = 0; j < 4; j++) acc[i][j] = 0.f;
    for (int kt = 0; kt < MM; kt += 16) {
        float4 av = *(const float4*)&Z[((size_t)bh * MM + i0 + aR) * MM + kt + aK];
        As[aK + 0][aR] = av.x; As[aK + 1][aR] = av.y;
        As[aK + 2][aR] = av.z; As[aK + 3][aR] = av.w;
        float4 bv = *(const float4*)&g_a3v[((size_t)bh * MM + kt + bK) * DH + bC];
        *(float4*)&Bs[bK][bC] = bv;
        __syncthreads();
        #pragma unroll
        for (int kk = 0; kk < 16; kk++) {
            float a[4], b[4];
            *(float4*)a = *(float4*)&As[kk][ty * 4];
            *(float4*)b = *(float4*)&Bs[kk][tx * 4];
            #pragma unroll
            for (int i = 0; i < 4; i++)
                #pragma unroll
                for (int j = 0; j < 4; j++) acc[i][j] += a[i] * b[j];
        }
        __syncthreads();
    }
    #pragma unroll
    for (int ii = 0; ii < 4; ii++)
        #pragma unroll
        for (int jj = 0; jj < 4; jj++)
            g_w2[((size_t)bh * MM + i0 + ty * 4 + ii) * DH + tx * 4 + jj] = acc[ii][jj];
}

// fused: out1 = softmax(q @ k_l^T) @ W2, 32 q-rows per block
__global__ __launch_bounds__(256) void a1out_kernel() {
    extern __shared__ float sm[];
    float* kls = sm;                    // 256*64
    float* w2s = sm + 16384;            // 256*64
    float* qs  = sm + 32768;            // 32*65
    float* sc  = sm + 32768 + 2080;     // 32*257
    __shared__ float pm[256];
    __shared__ float rmax[32], rinv[32];
    int bh = blockIdx.y;
    int n0 = blockIdx.x * 32;
    int tid = threadIdx.x;
    {
        const float4* klg = (const float4*)&g_kl[(size_t)bh * MM * DH];
        const float4* wg  = (const float4*)&g_w2[(size_t)bh * MM * DH];
        float4* kl4 = (float4*)kls;
        float4* w4  = (float4*)w2s;
        #pragma unroll
        for (int u = 0; u < 16; u++) {
            kl4[tid + u * 256] = klg[tid + u * 256];
            w4[tid + u * 256]  = wg[tid + u * 256];
        }
        #pragma unroll
        for (int u = 0; u < 8; u++) {
            int e = tid + u * 256;
            int r = e >> 6, d = e & 63;
            qs[r * 65 + d] = g_q[((size_t)bh * NSEQ + n0 + r) * DH + d];
        }
    }
    __syncthreads();
    int r = tid & 31, g = tid >> 5, j0 = g * 32;
    float sacc[32];
    #pragma unroll
    for (int jj = 0; jj < 32; jj++) sacc[jj] = 0.f;
    for (int d = 0; d < DH; d++) {
        float qv = qs[r * 65 + d];
        #pragma unroll
        for (int jj = 0; jj < 32; jj++) sacc[jj] += qv * kls[(j0 + jj) * 64 + d];
    }
    float lm = -1e30f;
    #pragma unroll
    for (int jj = 0; jj < 32; jj++) lm = fmaxf(lm, sacc[jj]);
    pm[tid] = lm;
    __syncthreads();
    if (tid < 32) {
        float m = pm[tid];
        #pragma unroll
        for (int gg = 1; gg < 8; gg++) m = fmaxf(m, pm[gg * 32 + tid]);
        rmax[tid] = m;
    }
    __syncthreads();
    float m = rmax[r];
    float ls = 0.f;
    #pragma unroll
    for (int jj = 0; jj < 32; jj++) {
        float e = __expf(sacc[jj] - m);
        sc[r * 257 + j0 + jj] = e;
        ls += e;
    }
    pm[tid] = ls;
    __syncthreads();
    if (tid < 32) {
        float s2 = 0.f;
        #pragma unroll
        for (int gg = 0; gg < 8; gg++) s2 += pm[gg * 32 + tid];
        rinv[tid] = 1.f / s2;
    }
    __syncthreads();
    int ro = tid >> 3, dg = tid & 7;
    float acc[8];
    #pragma unroll
    for (int dd = 0; dd < 8; dd++) acc[dd] = 0.f;
    for (int j = 0; j < MM; j++) {
        float p = sc[ro * 257 + j];
        const float* wrow = &w2s[j * 64 + dg * 8];
        #pragma unroll
        for (int dd = 0; dd < 8; dd++) acc[dd] += p * wrow[dd];
    }
    float inv = rinv[ro];
    size_t ob = ((size_t)bh * NSEQ + n0 + ro) * DH + dg * 8;
    #pragma unroll
    for (int dd = 0; dd < 8; dd++) g_out1[ob + dd] = acc[dd] * inv;
}

// depthwise conv over sequence (kernel 33, same pad), out1 += conv(v)
__global__ __launch_bounds__(256) void conv_kernel(const float* __restrict__ wres) {
    __shared__ float sv[160 * 64];
    __shared__ float wl[KERN];
    int bh = blockIdx.y, h = bh & 1;
    int n0 = blockIdx.x * 128;
    int tid = threadIdx.x;
    if (tid < KERN) wl[tid] = wres[h * KERN + tid];
    #pragma unroll
    for (int u = 0; u < 10; u++) {
        int e4 = tid + u * 256;
        int li = e4 >> 4, d4 = (e4 & 15) * 4;
        int n = n0 - 16 + li;
        float4 val = make_float4(0.f, 0.f, 0.f, 0.f);
        if (n >= 0 && n < NSEQ) val = *(const float4*)&g_v[((size_t)bh * NSEQ + n) * DH + d4];
        *(float4*)&sv[li * 64 + d4] = val;
    }
    __syncthreads();
    int d = tid & 63, rg = tid >> 6;
    for (int i = 0; i < 32; i++) {
        int rl = rg * 32 + i;
        float s = 0.f;
        #pragma unroll
        for (int t = 0; t < KERN; t++) s += wl[t] * sv[(rl + t) * 64 + d];
        g_out1[((size_t)bh * NSEQ + n0 + rl) * DH + d] += s;
    }
}

// final: out = x + (gather(out1) @ w_out + b_out)
__global__ __launch_bounds__(256) void outgemm_kernel(const float* __restrict__ x,
                                                      const float* __restrict__ wout,
                                                      const float* __restrict__ bout,
                                                      float* __restrict__ out) {
    __shared__ float As[8][132];
    __shared__ float Bs[8][132];
    int tid = threadIdx.x;
    int row0 = blockIdx.x * 128, col0 = blockIdx.y * 128;
    int aRow = tid >> 1, aK = (tid & 1) * 4;
    int bK = tid >> 5, bCol = (tid & 31) * 4;
    int ty = tid >> 4, tx = tid & 15;
    int tokA = row0 + aRow;
    int bbA = tokA >> 13, nA = tokA & 8191;
    float acc[8][8];
    #pragma unroll
    for (int i = 0; i < 8; i++)
        #pragma unroll
        for (int j = 0; j < 8; j++) acc[i][j] = 0.f;
    for (int kt = 0; kt < INNER; kt += 8) {
        int c = kt + aK;
        int h = c >> 6, d = c & 63;
        float4 av = *(const float4*)&g_out1[(((size_t)(bbA * HH + h)) * NSEQ + nA) * DH + d];
        As[aK + 0][aRow] = av.x; As[aK + 1][aRow] = av.y;
        As[aK + 2][aRow] = av.z; As[aK + 3][aRow] = av.w;
        float4 bv = *(const float4*)&wout[(size_t)(kt + bK) * DD + col0 + bCol];
        *(float4*)&Bs[bK][bCol] = bv;
        __syncthreads();
        #pragma unroll
        for (int kk = 0; kk < 8; kk++) {
            float a[8], b[8];
            *(float4*)(a)     = *(float4*)&As[kk][ty * 8];
            *(float4*)(a + 4) = *(float4*)&As[kk][ty * 8 + 4];
            *(float4*)(b)     = *(float4*)&Bs[kk][tx * 8];
            *(float4*)(b + 4) = *(float4*)&Bs[kk][tx * 8 + 4];
            #pragma unroll
            for (int i = 0; i < 8; i++)
                #pragma unroll
                for (int j = 0; j < 8; j++) acc[i][j] += a[i] * b[j];
        }
        __syncthreads();
    }
    #pragma unroll
    for (int i = 0; i < 8; i++) {
        int tok = row0 + ty * 8 + i;
        #pragma unroll
        for (int j = 0; j < 8; j++) {
            int c = col0 + tx * 8 + j;
            out[(size_t)tok * DD + c] = acc[i][j] + bout[c] + x[(size_t)tok * DD + c];
        }
    }
}

// ---------------- launch ----------------
extern "C" void kernel_launch(void* const* d_in, const int* in_sizes, int n_in,
                              void* d_out, int out_size) {
    const float* x     = (const float*)d_in[0];
    const float* gamma = (const float*)d_in[1];
    const float* beta  = (const float*)d_in[2];
    const float* wqkv  = (const float*)d_in[3];
    const float* wout  = (const float*)d_in[4];
    const float* bout  = (const float*)d_in[5];
    const float* wres  = (const float*)d_in[6];
    float* out = (float*)d_out;

    float *pA2, *pXZ, *pT1, *pT2, *pZA, *pZB;
    cudaGetSymbolAddress((void**)&pA2, g_a2);
    cudaGetSymbolAddress((void**)&pXZ, g_xz);
    cudaGetSymbolAddress((void**)&pT1, g_t1);
    cudaGetSymbolAddress((void**)&pT2, g_t2);
    cudaGetSymbolAddress((void**)&pZA, g_za);
    cudaGetSymbolAddress((void**)&pZB, g_zb);

    cudaFuncSetAttribute(sim3_kernel, cudaFuncAttributeMaxDynamicSharedMemorySize, 51200);
    cudaFuncSetAttribute(a1out_kernel, cudaFuncAttributeMaxDynamicSharedMemorySize, 172288);

    init_kernel<<<1, 1>>>();
    ln_kernel<<<TOK, 128>>>(x, gamma, beta);
    qkv_kernel<<<dim3(TOK / 128, 3), 256>>>(wqkv);
    landmark_kernel<<<dim3(BH, MM), 64>>>();
    sim2_kernel<<<BH * MM, 256>>>();
    absmax_kernel<<<dim3(BH, 2), 256>>>();
    zinit_kernel<<<BH * MM, 256>>>();

    float* zc = pZA;
    float* zn = pZB;
    for (int it = 0; it < 6; it++) {
        bmm_kernel<<<dim3(4, 4, BH), 256>>>(pA2, zc, pXZ, 1.f, 0.f, 0.f);
        bmm_kernel<<<dim3(4, 4, BH), 256>>>(pXZ, pXZ, pT1, 1.f, -7.f, 15.f);
        bmm_kernel<<<dim3(4, 4, BH), 256>>>(pXZ, pT1, pT2, -1.f, 0.f, 13.f);
        bmm_kernel<<<dim3(4, 4, BH), 256>>>(zc, pT2, zn, 0.25f, 0.f, 0.f);
        float* t = zc; zc = zn; zn = t;
    }

    sim3_kernel<<<dim3(4, 64, BH), 256, 51200>>>();
    softmaxN_kernel<<<BH * MM, 256>>>();
    a3vpart_kernel<<<dim3(4, 8, BH), 256>>>();
    a3vred_kernel<<<512, 256>>>();
    w2_kernel<<<dim3(4, BH), 256>>>(zc);
    a1out_kernel<<<dim3(NSEQ / 32, BH), 256, 172288>>>();
    conv_kernel<<<dim3(NSEQ / 128, BH), 256>>>(wres);
    outgemm_kernel<<<dim3(TOK / 128, 4), 256>>>(x, wout, bout, out);
}

// round 3
// speedup vs baseline: 2.5007x; 2.4985x over previous
#include <cuda_runtime.h>
#include <math.h>

#define BB 4
#define NSEQ 8192
#define DD 512
#define HH 2
#define DH 64
#define INNER 128
#define MM 256
#define LLM 32
#define BH (BB*HH)
#define TOK (BB*NSEQ)
#define KERN 33

__device__ float g_xn[(size_t)TOK*DD];
__device__ float g_q[(size_t)BH*NSEQ*DH];
__device__ float g_k[(size_t)BH*NSEQ*DH];
__device__ float g_v[(size_t)BH*NSEQ*DH];
__device__ float g_ql[BH*MM*DH];
__device__ float g_kl[BH*MM*DH];
__device__ float g_a2[BH*MM*MM];
__device__ float g_xz[BH*MM*MM];
__device__ float g_t1[BH*MM*MM];
__device__ float g_t2[BH*MM*MM];
__device__ float g_za[BH*MM*MM];
__device__ float g_zb[BH*MM*MM];
__device__ float g_sim[(size_t)BH*MM*NSEQ];
__device__ float g_a3v[BH*MM*DH];
__device__ float g_w2[BH*MM*DH];
__device__ float g_out1[(size_t)BH*NSEQ*DH];
__device__ float g_part[BH*8*MM*DH];
__device__ unsigned g_max0, g_max1;

__device__ __forceinline__ unsigned f2tf(float f) {
    unsigned r; asm("cvt.rna.tf32.f32 %0, %1;" : "=r"(r) : "f"(f)); return r;
}
__device__ __forceinline__ void mma8(float* c, const unsigned* a, const unsigned* b) {
    asm volatile("mma.sync.aligned.m16n8k8.row.col.f32.tf32.tf32.f32 "
        "{%0,%1,%2,%3}, {%4,%5,%6,%7}, {%8,%9}, {%0,%1,%2,%3};"
        : "+f"(c[0]), "+f"(c[1]), "+f"(c[2]), "+f"(c[3])
        : "r"(a[0]), "r"(a[1]), "r"(a[2]), "r"(a[3]), "r"(b[0]), "r"(b[1]));
}

__global__ void init_kernel() { g_max0 = 0u; g_max1 = 0u; }

__global__ __launch_bounds__(128) void ln_kernel(const float* __restrict__ x,
                                                 const float* __restrict__ gamma,
                                                 const float* __restrict__ beta) {
    int t = blockIdx.x, tid = threadIdx.x;
    const float4* xr = (const float4*)(x + (size_t)t * DD);
    float4 v = xr[tid];
    float s  = v.x + v.y + v.z + v.w;
    float sq = v.x*v.x + v.y*v.y + v.z*v.z + v.w*v.w;
    __shared__ float sb[8];
    #pragma unroll
    for (int o = 16; o; o >>= 1) {
        s  += __shfl_xor_sync(0xffffffffu, s, o);
        sq += __shfl_xor_sync(0xffffffffu, sq, o);
    }
    int w = tid >> 5, l = tid & 31;
    if (l == 0) { sb[w] = s; sb[4 + w] = sq; }
    __syncthreads();
    if (tid == 0) { sb[0] = sb[0]+sb[1]+sb[2]+sb[3]; sb[4] = sb[4]+sb[5]+sb[6]+sb[7]; }
    __syncthreads();
    float mu  = sb[0] * (1.f / DD);
    float var = sb[4] * (1.f / DD) - mu * mu;
    float rs  = rsqrtf(var + 1e-5f);
    float4 g4 = ((const float4*)gamma)[tid];
    float4 b4 = ((const float4*)beta)[tid];
    float4 o;
    o.x = (v.x - mu) * rs * g4.x + b4.x;
    o.y = (v.y - mu) * rs * g4.y + b4.y;
    o.z = (v.z - mu) * rs * g4.z + b4.z;
    o.w = (v.w - mu) * rs * g4.w + b4.w;
    ((float4*)(g_xn + (size_t)t * DD))[tid] = o;
}

__global__ void landmark_kernel() {
    int bh = blockIdx.x, m = blockIdx.y, d = threadIdx.x;
    size_t base = ((size_t)bh * NSEQ + m * LLM) * DH + d;
    float sq = 0.f, sk = 0.f;
    #pragma unroll 8
    for (int i = 0; i < LLM; i++) { sq += g_q[base + (size_t)i * DH]; sk += g_k[base + (size_t)i * DH]; }
    g_ql[(bh * MM + m) * DH + d] = sq * (1.f / LLM);
    g_kl[(bh * MM + m) * DH + d] = sk * (1.f / LLM);
}

__global__ __launch_bounds__(256) void sim2_kernel() {
    int bh = blockIdx.x >> 8, i = blockIdx.x & 255;
    int tid = threadIdx.x;
    __shared__ float qs[DH];
    __shared__ float red[8];
    if (tid < DH) qs[tid] = g_ql[(bh * MM + i) * DH + tid];
    __syncthreads();
    const float* kr = &g_kl[(bh * MM + tid) * DH];
    float s = 0.f;
    #pragma unroll
    for (int d = 0; d < DH; d += 4) {
        float4 kv = *(const float4*)&kr[d];
        s += qs[d]*kv.x + qs[d+1]*kv.y + qs[d+2]*kv.z + qs[d+3]*kv.w;
    }
    float m = s;
    #pragma unroll
    for (int o = 16; o; o >>= 1) m = fmaxf(m, __shfl_xor_sync(0xffffffffu, m, o));
    int w = tid >> 5, l = tid & 31;
    if (l == 0) red[w] = m;
    __syncthreads();
    if (w == 0) {
        float t = red[l & 7];
        #pragma unroll
        for (int o = 4; o; o >>= 1) t = fmaxf(t, __shfl_xor_sync(0xffffffffu, t, o));
        if (l == 0) red[0] = t;
    }
    __syncthreads();
    m = red[0];
    __syncthreads();
    float e = __expf(s - m);
    float su = e;
    #pragma unroll
    for (int o = 16; o; o >>= 1) su += __shfl_xor_sync(0xffffffffu, su, o);
    if (l == 0) red[w] = su;
    __syncthreads();
    if (w == 0) {
        float t = red[l & 7];
        #pragma unroll
        for (int o = 4; o; o >>= 1) t += __shfl_xor_sync(0xffffffffu, t, o);
        if (l == 0) red[0] = t;
    }
    __syncthreads();
    g_a2[((size_t)bh * MM + i) * MM + tid] = e / red[0];
}

__global__ __launch_bounds__(256) void absmax_kernel() {
    int bh = blockIdx.x, mode = blockIdx.y, tid = threadIdx.x;
    const float* A = &g_a2[(size_t)bh * MM * MM];
    float s = 0.f;
    if (mode == 0) { for (int j = 0; j < MM; j++) s += fabsf(A[tid * MM + j]); }
    else           { for (int i = 0; i < MM; i++) s += fabsf(A[i * MM + tid]); }
    float m = s;
    #pragma unroll
    for (int o = 16; o; o >>= 1) m = fmaxf(m, __shfl_xor_sync(0xffffffffu, m, o));
    __shared__ float red[8];
    int w = tid >> 5, l = tid & 31;
    if (l == 0) red[w] = m;
    __syncthreads();
    if (tid == 0) {
        float t = red[0];
        for (int u = 1; u < 8; u++) t = fmaxf(t, red[u]);
        atomicMax(mode == 0 ? &g_max0 : &g_max1, __float_as_uint(t));
    }
}

__global__ __launch_bounds__(256) void zinit_kernel() {
    int bh = blockIdx.x >> 8, i = blockIdx.x & 255, j = threadIdx.x;
    float inv = 1.f / (__uint_as_float(g_max0) * __uint_as_float(g_max1));
    g_za[((size_t)bh * MM + i) * MM + j] = g_a2[((size_t)bh * MM + j) * MM + i] * inv;
}

__global__ __launch_bounds__(256) void softmaxN_kernel() {
    __shared__ float buf[NSEQ];
    __shared__ float red[8];
    int tid = threadIdx.x;
    float* row = &g_sim[(size_t)blockIdx.x * NSEQ];
    float4* b4 = (float4*)buf;
    const float4* r4 = (const float4*)row;
    float lm = -1e30f;
    #pragma unroll
    for (int u = 0; u < 8; u++) {
        float4 v = r4[tid + u * 256];
        b4[tid + u * 256] = v;
        lm = fmaxf(lm, fmaxf(fmaxf(v.x, v.y), fmaxf(v.z, v.w)));
    }
    #pragma unroll
    for (int o = 16; o; o >>= 1) lm = fmaxf(lm, __shfl_xor_sync(0xffffffffu, lm, o));
    int w = tid >> 5, l = tid & 31;
    if (l == 0) red[w] = lm;
    __syncthreads();
    if (tid == 0) { float t = red[0]; for (int u = 1; u < 8; u++) t = fmaxf(t, red[u]); red[0] = t; }
    __syncthreads();
    float m = red[0];
    __syncthreads();
    float ls = 0.f;
    for (int i = tid; i < NSEQ; i += 256) { float e = __expf(buf[i] - m); buf[i] = e; ls += e; }
    #pragma unroll
    for (int o = 16; o; o >>= 1) ls += __shfl_xor_sync(0xffffffffu, ls, o);
    if (l == 0) red[w] = ls;
    __syncthreads();
    if (tid == 0) { float t = 0.f; for (int u = 0; u < 8; u++) t += red[u]; red[0] = 1.f / t; }
    __syncthreads();
    float inv = red[0];
    float4* o4 = (float4*)row;
    #pragma unroll
    for (int u = 0; u < 8; u++) {
        float4 v = b4[tid + u * 256];
        v.x *= inv; v.y *= inv; v.z *= inv; v.w *= inv;
        o4[tid + u * 256] = v;
    }
}

// softmax over rows of 256 (sim1), one warp per row
__global__ __launch_bounds__(256) void softmax256_kernel() {
    int row = blockIdx.x * 8 + (threadIdx.x >> 5);
    int lane = threadIdx.x & 31;
    float4* r = (float4*)&g_sim[(size_t)row * 256];
    float4 v0 = r[lane], v1 = r[lane + 32];
    float m = fmaxf(fmaxf(fmaxf(v0.x, v0.y), fmaxf(v0.z, v0.w)),
                    fmaxf(fmaxf(v1.x, v1.y), fmaxf(v1.z, v1.w)));
    #pragma unroll
    for (int o = 16; o; o >>= 1) m = fmaxf(m, __shfl_xor_sync(0xffffffffu, m, o));
    v0.x = __expf(v0.x-m); v0.y = __expf(v0.y-m); v0.z = __expf(v0.z-m); v0.w = __expf(v0.w-m);
    v1.x = __expf(v1.x-m); v1.y = __expf(v1.y-m); v1.z = __expf(v1.z-m); v1.w = __expf(v1.w-m);
    float s = v0.x+v0.y+v0.z+v0.w+v1.x+v1.y+v1.z+v1.w;
    #pragma unroll
    for (int o = 16; o; o >>= 1) s += __shfl_xor_sync(0xffffffffu, s, o);
    float inv = 1.f / s;
    v0.x*=inv; v0.y*=inv; v0.z*=inv; v0.w*=inv;
    v1.x*=inv; v1.y*=inv; v1.z*=inv; v1.w*=inv;
    r[lane] = v0; r[lane + 32] = v1;
}

__global__ void a3vred_kernel() {
    int e = blockIdx.x * 256 + threadIdx.x;
    int bh = e >> 14, r = e & 16383;
    float s = 0.f;
    #pragma unroll
    for (int ks = 0; ks < 8; ks++) s += g_part[((size_t)bh * 8 + ks) * 16384 + r];
    g_a3v[e] = s;
}

__global__ __launch_bounds__(256) void conv_kernel(const float* __restrict__ wres) {
    __shared__ float sv[160 * 64];
    __shared__ float wl[KERN];
    int bh = blockIdx.y, h = bh & 1;
    int n0 = blockIdx.x * 128;
    int tid = threadIdx.x;
    if (tid < KERN) wl[tid] = wres[h * KERN + tid];
    #pragma unroll
    for (int u = 0; u < 10; u++) {
        int e4 = tid + u * 256;
        int li = e4 >> 4, d4 = (e4 & 15) * 4;
        int n = n0 - 16 + li;
        float4 val = make_float4(0.f, 0.f, 0.f, 0.f);
        if (n >= 0 && n < NSEQ) val = *(const float4*)&g_v[((size_t)bh * NSEQ + n) * DH + d4];
        *(float4*)&sv[li * 64 + d4] = val;
    }
    __syncthreads();
    int d = tid & 63, rg = tid >> 6;
    for (int i = 0; i < 32; i++) {
        int rl = rg * 32 + i;
        float s = 0.f;
        #pragma unroll
        for (int t = 0; t < KERN; t++) s += wl[t] * sv[(rl + t) * 64 + d];
        g_out1[((size_t)bh * NSEQ + n0 + rl) * DH + d] += s;
    }
}

// ---------- tf32 MMA kernels ----------

// qkv: xn(32768x512)@wqkv(512x384). BM=128 BN=128 BK=32, double buffered.
__global__ __launch_bounds__(256) void qkv_mma(const float* __restrict__ wqkv) {
    extern __shared__ unsigned sm[];
    int tid = threadIdx.x;
    int row0 = blockIdx.x * 128, col0 = blockIdx.y * 128;
    int lane = tid & 31, wid = tid >> 5;
    int g = lane >> 2, t = lane & 3;
    int wm = (wid & 1) * 64, wn = (wid >> 1) * 32;
    float acc[4][4][4];
    #pragma unroll
    for (int i = 0; i < 4; i++) for (int j = 0; j < 4; j++) for (int u = 0; u < 4; u++) acc[i][j][u] = 0.f;
    float4 aR[4], bR[4];
    auto LOAD = [&](int kt) {
        #pragma unroll
        for (int p = 0; p < 4; p++) {
            int idx = tid + p * 256; int m = idx >> 3, c = (idx & 7) * 4;
            aR[p] = *(const float4*)&g_xn[(size_t)(row0 + m) * DD + kt + c];
        }
        #pragma unroll
        for (int p = 0; p < 4; p++) {
            int idx = tid + p * 256; int k = idx >> 5, c = (idx & 31) * 4;
            bR[p] = *(const float4*)&wqkv[(size_t)(kt + k) * 384 + col0 + c];
        }
    };
    auto STS = [&](unsigned* st) {
        unsigned* As = st; unsigned* Bs = st + 4608;
        #pragma unroll
        for (int p = 0; p < 4; p++) {
            int idx = tid + p * 256; int m = idx >> 3, c = (idx & 7) * 4;
            *(uint4*)&As[m*36+c] = make_uint4(f2tf(aR[p].x), f2tf(aR[p].y), f2tf(aR[p].z), f2tf(aR[p].w));
        }
        #pragma unroll
        for (int p = 0; p < 4; p++) {
            int idx = tid + p * 256; int k = idx >> 5, c = (idx & 31) * 4;
            *(uint4*)&Bs[k*136+c] = make_uint4(f2tf(bR[p].x), f2tf(bR[p].y), f2tf(bR[p].z), f2tf(bR[p].w));
        }
    };
    auto COMP = [&](const unsigned* st) {
        const unsigned* As = st; const unsigned* Bs = st + 4608;
        #pragma unroll
        for (int s = 0; s < 4; s++) {
            unsigned af[4][4], bf[4][2];
            #pragma unroll
            for (int i = 0; i < 4; i++) {
                const unsigned* p = &As[(wm + 16*i + g)*36 + 8*s + t];
                af[i][0] = p[0]; af[i][1] = p[288]; af[i][2] = p[4]; af[i][3] = p[292];
            }
            #pragma unroll
            for (int j = 0; j < 4; j++) {
                const unsigned* p = &Bs[(8*s + t)*136 + wn + 8*j + g];
                bf[j][0] = p[0]; bf[j][1] = p[544];
            }
            #pragma unroll
            for (int i = 0; i < 4; i++)
                #pragma unroll
                for (int j = 0; j < 4; j++) mma8(acc[i][j], af[i], bf[j]);
        }
    };
    LOAD(0); STS(sm); __syncthreads();
    for (int it = 0; it < 16; it++) {
        if (it + 1 < 16) LOAD((it + 1) * 32);
        COMP(sm + (it & 1) * 8960);
        if (it + 1 < 16) { STS(sm + ((it + 1) & 1) * 8960); __syncthreads(); }
    }
    auto STORE = [&](int tok, int c, float v) {
        int bb = tok >> 13, n = tok & 8191;
        int which = c >> 7, hd = c & 127, h = hd >> 6, d = hd & 63;
        size_t dst = (((size_t)(bb * HH + h)) * NSEQ + n) * DH + d;
        if (which == 0)      g_q[dst] = v * 0.125f;
        else if (which == 1) g_k[dst] = v;
        else                 g_v[dst] = v;
    };
    #pragma unroll
    for (int i = 0; i < 4; i++) {
        int row = row0 + wm + 16*i + g;
        #pragma unroll
        for (int j = 0; j < 4; j++) {
            int col = col0 + wn + 8*j + 2*t;
            STORE(row, col, acc[i][j][0]);
            STORE(row, col + 1, acc[i][j][1]);
            STORE(row + 8, col, acc[i][j][2]);
            STORE(row + 8, col + 1, acc[i][j][3]);
        }
    }
}

// outgemm: gather(out1)(32768x128)@wout(128x512) + bias + x
__global__ __launch_bounds__(256) void outgemm_mma(const float* __restrict__ x,
                                                   const float* __restrict__ wout,
                                                   const float* __restrict__ bout,
                                                   float* __restrict__ out) {
    extern __shared__ unsigned sm[];
    int tid = threadIdx.x;
    int row0 = blockIdx.x * 128, col0 = blockIdx.y * 128;
    int lane = tid & 31, wid = tid >> 5;
    int g = lane >> 2, t = lane & 3;
    int wm = (wid & 1) * 64, wn = (wid >> 1) * 32;
    float acc[4][4][4];
    #pragma unroll
    for (int i = 0; i < 4; i++) for (int j = 0; j < 4; j++) for (int u = 0; u < 4; u++) acc[i][j][u] = 0.f;
    float4 aR[4], bR[4];
    auto LOAD = [&](int kt) {
        #pragma unroll
        for (int p = 0; p < 4; p++) {
            int idx = tid + p * 256; int m = idx >> 3, c = (idx & 7) * 4;
            int tok = row0 + m; int bb = tok >> 13, n = tok & 8191;
            int k = kt + c; int h = k >> 6, d = k & 63;
            aR[p] = *(const float4*)&g_out1[(((size_t)(bb * HH + h)) * NSEQ + n) * DH + d];
        }
        #pragma unroll
        for (int p = 0; p < 4; p++) {
            int idx = tid + p * 256; int k = idx >> 5, c = (idx & 31) * 4;
            bR[p] = *(const float4*)&wout[(size_t)(kt + k) * DD + col0 + c];
        }
    };
    auto STS = [&](unsigned* st) {
        unsigned* As = st; unsigned* Bs = st + 4608;
        #pragma unroll
        for (int p = 0; p < 4; p++) {
            int idx = tid + p * 256; int m = idx >> 3, c = (idx & 7) * 4;
            *(uint4*)&As[m*36+c] = make_uint4(f2tf(aR[p].x), f2tf(aR[p].y), f2tf(aR[p].z), f2tf(aR[p].w));
        }
        #pragma unroll
        for (int p = 0; p < 4; p++) {
            int idx = tid + p * 256; int k = idx >> 5, c = (idx & 31) * 4;
            *(uint4*)&Bs[k*136+c] = make_uint4(f2tf(bR[p].x), f2tf(bR[p].y), f2tf(bR[p].z), f2tf(bR[p].w));
        }
    };
    auto COMP = [&](const unsigned* st) {
        const unsigned* As = st; const unsigned* Bs = st + 4608;
        #pragma unroll
        for (int s = 0; s < 4; s++) {
            unsigned af[4][4], bf[4][2];
            #pragma unroll
            for (int i = 0; i < 4; i++) {
                const unsigned* p = &As[(wm + 16*i + g)*36 + 8*s + t];
                af[i][0] = p[0]; af[i][1] = p[288]; af[i][2] = p[4]; af[i][3] = p[292];
            }
            #pragma unroll
            for (int j = 0; j < 4; j++) {
                const unsigned* p = &Bs[(8*s + t)*136 + wn + 8*j + g];
                bf[j][0] = p[0]; bf[j][1] = p[544];
            }
            #pragma unroll
            for (int i = 0; i < 4; i++)
                #pragma unroll
                for (int j = 0; j < 4; j++) mma8(acc[i][j], af[i], bf[j]);
        }
    };
    LOAD(0); STS(sm); __syncthreads();
    for (int it = 0; it < 4; it++) {
        if (it + 1 < 4) LOAD((it + 1) * 32);
        COMP(sm + (it & 1) * 8960);
        if (it + 1 < 4) { STS(sm + ((it + 1) & 1) * 8960); __syncthreads(); }
    }
    #pragma unroll
    for (int i = 0; i < 4; i++) {
        int row = row0 + wm + 16*i + g;
        #pragma unroll
        for (int j = 0; j < 4; j++) {
            int col = col0 + wn + 8*j + 2*t;
            out[(size_t)row*DD + col]         = acc[i][j][0] + bout[col]   + x[(size_t)row*DD + col];
            out[(size_t)row*DD + col+1]       = acc[i][j][1] + bout[col+1] + x[(size_t)row*DD + col+1];
            out[(size_t)(row+8)*DD + col]     = acc[i][j][2] + bout[col]   + x[(size_t)(row+8)*DD + col];
            out[(size_t)(row+8)*DD + col+1]   = acc[i][j][3] + bout[col+1] + x[(size_t)(row+8)*DD + col+1];
        }
    }
}

// NT, K=64: C[M x N] = A[M x 64] @ B[N x 64]^T per batch. grid(M/128, N/128, BH)
__global__ __launch_bounds__(256) void nt64_mma(const float* __restrict__ A,
                                                const float* __restrict__ B,
                                                float* __restrict__ C) {
    extern __shared__ unsigned sm[];
    unsigned* As = sm;
    unsigned* Bs = sm + 8704;
    int M = gridDim.x * 128, N = gridDim.y * 128;
    int bh = blockIdx.z;
    const float* Ab = A + (size_t)bh * M * 64 + (size_t)blockIdx.x * 128 * 64;
    const float* Bb = B + (size_t)bh * N * 64 + (size_t)blockIdx.y * 128 * 64;
    int tid = threadIdx.x;
    #pragma unroll
    for (int p = 0; p < 8; p++) {
        int idx = tid + p * 256; int m = idx >> 4, c = (idx & 15) * 4;
        float4 v = *(const float4*)&Ab[(size_t)m * 64 + c];
        *(uint4*)&As[m*68+c] = make_uint4(f2tf(v.x), f2tf(v.y), f2tf(v.z), f2tf(v.w));
        v = *(const float4*)&Bb[(size_t)m * 64 + c];
        *(uint4*)&Bs[m*68+c] = make_uint4(f2tf(v.x), f2tf(v.y), f2tf(v.z), f2tf(v.w));
    }
    __syncthreads();
    int lane = tid & 31, wid = tid >> 5;
    int g = lane >> 2, t = lane & 3;
    int wm = (wid & 1) * 64, wn = (wid >> 1) * 32;
    float acc[4][4][4];
    #pragma unroll
    for (int i = 0; i < 4; i++) for (int j = 0; j < 4; j++) for (int u = 0; u < 4; u++) acc[i][j][u] = 0.f;
    #pragma unroll
    for (int s = 0; s < 8; s++) {
        unsigned af[4][4], bf[4][2];
        #pragma unroll
        for (int i = 0; i < 4; i++) {
            const unsigned* p = &As[(wm + 16*i + g)*68 + 8*s + t];
            af[i][0] = p[0]; af[i][1] = p[544]; af[i][2] = p[4]; af[i][3] = p[548];
        }
        #pragma unroll
        for (int j = 0; j < 4; j++) {
            const unsigned* p = &Bs[(wn + 8*j + g)*68 + 8*s + t];
            bf[j][0] = p[0]; bf[j][1] = p[4];
        }
        #pragma unroll
        for (int i = 0; i < 4; i++)
            #pragma unroll
            for (int j = 0; j < 4; j++) mma8(acc[i][j], af[i], bf[j]);
    }
    float* Cb = C + (size_t)bh * M * N + (size_t)blockIdx.x * 128 * N + blockIdx.y * 128;
    #pragma unroll
    for (int i = 0; i < 4; i++) {
        int row = wm + 16*i + g;
        #pragma unroll
        for (int j = 0; j < 4; j++) {
            int col = wn + 8*j + 2*t;
            Cb[(size_t)row*N + col]       = acc[i][j][0];
            Cb[(size_t)row*N + col+1]     = acc[i][j][1];
            Cb[(size_t)(row+8)*N + col]   = acc[i][j][2];
            Cb[(size_t)(row+8)*N + col+1] = acc[i][j][3];
        }
    }
}

// NN, N=64: C[64 x 64]-tile = A[M x K] @ B[K x 64] (optionally split-K via grid.y).
// grid(M/64, ksplits, BH), 128 threads.
__global__ __launch_bounds__(128) void nn64_mma(const float* __restrict__ A,
                                                const float* __restrict__ B,
                                                float* __restrict__ C,
                                                int lda, size_t aBatch, size_t bBatch,
                                                size_t cBatch, size_t cSplit, int kchunk) {
    __shared__ unsigned As[64*36];
    __shared__ unsigned Bs[32*72];
    int bh = blockIdx.z, ks = blockIdx.y;
    int m0 = blockIdx.x * 64;
    int kbeg = ks * kchunk;
    const float* Ab = A + (size_t)bh * aBatch + (size_t)m0 * lda + kbeg;
    const float* Bb = B + (size_t)bh * bBatch + (size_t)kbeg * 64;
    int tid = threadIdx.x;
    int lane = tid & 31, wid = tid >> 5;
    int g = lane >> 2, t = lane & 3;
    int wm = (wid & 1) * 32, wn = (wid >> 1) * 32;
    float acc[2][4][4];
    #pragma unroll
    for (int i = 0; i < 2; i++) for (int j = 0; j < 4; j++) for (int u = 0; u < 4; u++) acc[i][j][u] = 0.f;
    int iters = kchunk / 32;
    for (int it = 0; it < iters; it++) {
        #pragma unroll
        for (int p = 0; p < 4; p++) {
            int idx = tid + p * 128; int m = idx >> 3, c = (idx & 7) * 4;
            float4 v = *(const float4*)&Ab[(size_t)m * lda + it*32 + c];
            *(uint4*)&As[m*36+c] = make_uint4(f2tf(v.x), f2tf(v.y), f2tf(v.z), f2tf(v.w));
        }
        #pragma unroll
        for (int p = 0; p < 4; p++) {
            int idx = tid + p * 128; int k = idx >> 4, c = (idx & 15) * 4;
            float4 v = *(const float4*)&Bb[(size_t)(it*32 + k) * 64 + c];
            *(uint4*)&Bs[k*72+c] = make_uint4(f2tf(v.x), f2tf(v.y), f2tf(v.z), f2tf(v.w));
        }
        __syncthreads();
        #pragma unroll
        for (int s = 0; s < 4; s++) {
            unsigned af[2][4], bf[4][2];
            #pragma unroll
            for (int i = 0; i < 2; i++) {
                const unsigned* p = &As[(wm + 16*i + g)*36 + 8*s + t];
                af[i][0] = p[0]; af[i][1] = p[288]; af[i][2] = p[4]; af[i][3] = p[292];
            }
            #pragma unroll
            for (int j = 0; j < 4; j++) {
                const unsigned* p = &Bs[(8*s + t)*72 + wn + 8*j + g];
                bf[j][0] = p[0]; bf[j][1] = p[288];
            }
            #pragma unroll
            for (int i = 0; i < 2; i++)
                #pragma unroll
                for (int j = 0; j < 4; j++) mma8(acc[i][j], af[i], bf[j]);
        }
        __syncthreads();
    }
    float* Cb = C + (size_t)bh * cBatch + (size_t)ks * cSplit + (size_t)m0 * 64;
    #pragma unroll
    for (int i = 0; i < 2; i++) {
        int row = wm + 16*i + g;
        #pragma unroll
        for (int j = 0; j < 4; j++) {
            int col = wn + 8*j + 2*t;
            Cb[(size_t)row*64 + col]       = acc[i][j][0];
            Cb[(size_t)row*64 + col+1]     = acc[i][j][1];
            Cb[(size_t)(row+8)*64 + col]   = acc[i][j][2];
            Cb[(size_t)(row+8)*64 + col+1] = acc[i][j][3];
        }
    }
}

// batched 256x256x256: C = alpha*(A@B) + beta*A + gamma*I. grid(4,4,BH), 128 thr.
__global__ __launch_bounds__(128) void bmm_mma(const float* __restrict__ A,
                                               const float* __restrict__ Bm,
                                               float* __restrict__ C,
                                               float alpha, float beta, float gam) {
    __shared__ unsigned As[64*36];
    __shared__ unsigned Bs[32*72];
    int bh = blockIdx.z;
    size_t base = (size_t)bh * MM * MM;
    int i0 = blockIdx.x * 64, j0 = blockIdx.y * 64;
    int tid = threadIdx.x;
    int lane = tid & 31, wid = tid >> 5;
    int g = lane >> 2, t = lane & 3;
    int wm = (wid & 1) * 32, wn = (wid >> 1) * 32;
    float acc[2][4][4];
    #pragma unroll
    for (int i = 0; i < 2; i++) for (int j = 0; j < 4; j++) for (int u = 0; u < 4; u++) acc[i][j][u] = 0.f;
    for (int it = 0; it < 8; it++) {
        #pragma unroll
        for (int p = 0; p < 4; p++) {
            int idx = tid + p * 128; int m = idx >> 3, c = (idx & 7) * 4;
            float4 v = *(const float4*)&A[base + (size_t)(i0 + m) * MM + it*32 + c];
            *(uint4*)&As[m*36+c] = make_uint4(f2tf(v.x), f2tf(v.y), f2tf(v.z), f2tf(v.w));
        }
        #pragma unroll
        for (int p = 0; p < 4; p++) {
            int idx = tid + p * 128; int k = idx >> 4, c = (idx & 15) * 4;
            float4 v = *(const float4*)&Bm[base + (size_t)(it*32 + k) * MM + j0 + c];
            *(uint4*)&Bs[k*72+c] = make_uint4(f2tf(v.x), f2tf(v.y), f2tf(v.z), f2tf(v.w));
        }
        __syncthreads();
        #pragma unroll
        for (int s = 0; s < 4; s++) {
            unsigned af[2][4], bf[4][2];
            #pragma unroll
            for (int i = 0; i < 2; i++) {
                const unsigned* p = &As[(wm + 16*i + g)*36 + 8*s + t];
                af[i][0] = p[0]; af[i][1] = p[288]; af[i][2] = p[4]; af[i][3] = p[292];
            }
            #pragma unroll
            for (int j = 0; j < 4; j++) {
                const unsigned* p = &Bs[(8*s + t)*72 + wn + 8*j + g];
                bf[j][0] = p[0]; bf[j][1] = p[288];
            }
            #pragma unroll
            for (int i = 0; i < 2; i++)
                #pragma unroll
                for (int j = 0; j < 4; j++) mma8(acc[i][j], af[i], bf[j]);
        }
        __syncthreads();
    }
    #pragma unroll
    for (int i = 0; i < 2; i++) {
        #pragma unroll
        for (int j = 0; j < 4; j++) {
            #pragma unroll
            for (int u = 0; u < 4; u++) {
                int row = i0 + wm + 16*i + g + (u >> 1) * 8;
                int col = j0 + wn + 8*j + 2*t + (u & 1);
                float r = alpha * acc[i][j][u];
                if (beta != 0.f) r += beta * A[base + (size_t)row * MM + col];
                if (row == col) r += gam;
                C[base + (size_t)row * MM + col] = r;
            }
        }
    }
}

// ---------------- launch ----------------
extern "C" void kernel_launch(void* const* d_in, const int* in_sizes, int n_in,
                              void* d_out, int out_size) {
    const float* x     = (const float*)d_in[0];
    const float* gamma = (const float*)d_in[1];
    const float* beta  = (const float*)d_in[2];
    const float* wqkv  = (const float*)d_in[3];
    const float* wout  = (const float*)d_in[4];
    const float* bout  = (const float*)d_in[5];
    const float* wres  = (const float*)d_in[6];
    float* out = (float*)d_out;

    float *pA2, *pXZ, *pT1, *pT2, *pZA, *pZB, *pQL, *pKL, *pQ, *pK, *pSIM, *pV, *pPART, *pA3V, *pW2, *pOUT1;
    cudaGetSymbolAddress((void**)&pA2, g_a2);
    cudaGetSymbolAddress((void**)&pXZ, g_xz);
    cudaGetSymbolAddress((void**)&pT1, g_t1);
    cudaGetSymbolAddress((void**)&pT2, g_t2);
    cudaGetSymbolAddress((void**)&pZA, g_za);
    cudaGetSymbolAddress((void**)&pZB, g_zb);
    cudaGetSymbolAddress((void**)&pQL, g_ql);
    cudaGetSymbolAddress((void**)&pKL, g_kl);
    cudaGetSymbolAddress((void**)&pQ, g_q);
    cudaGetSymbolAddress((void**)&pK, g_k);
    cudaGetSymbolAddress((void**)&pV, g_v);
    cudaGetSymbolAddress((void**)&pSIM, g_sim);
    cudaGetSymbolAddress((void**)&pPART, g_part);
    cudaGetSymbolAddress((void**)&pA3V, g_a3v);
    cudaGetSymbolAddress((void**)&pW2, g_w2);
    cudaGetSymbolAddress((void**)&pOUT1, g_out1);

    cudaFuncSetAttribute(qkv_mma, cudaFuncAttributeMaxDynamicSharedMemorySize, 71680);
    cudaFuncSetAttribute(outgemm_mma, cudaFuncAttributeMaxDynamicSharedMemorySize, 71680);
    cudaFuncSetAttribute(nt64_mma, cudaFuncAttributeMaxDynamicSharedMemorySize, 69632);

    init_kernel<<<1, 1>>>();
    ln_kernel<<<TOK, 128>>>(x, gamma, beta);
    qkv_mma<<<dim3(TOK / 128, 3), 256, 71680>>>(wqkv);
    landmark_kernel<<<dim3(BH, MM), 64>>>();
    sim2_kernel<<<BH * MM, 256>>>();
    absmax_kernel<<<dim3(BH, 2), 256>>>();
    zinit_kernel<<<BH * MM, 256>>>();

    float* zc = pZA;
    float* zn = pZB;
    for (int it = 0; it < 6; it++) {
        bmm_mma<<<dim3(4, 4, BH), 128>>>(pA2, zc, pXZ, 1.f, 0.f, 0.f);
        bmm_mma<<<dim3(4, 4, BH), 128>>>(pXZ, pXZ, pT1, 1.f, -7.f, 15.f);
        bmm_mma<<<dim3(4, 4, BH), 128>>>(pXZ, pT1, pT2, -1.f, 0.f, 13.f);
        bmm_mma<<<dim3(4, 4, BH), 128>>>(zc, pT2, zn, 0.25f, 0.f, 0.f);
        float* t = zc; zc = zn; zn = t;
    }

    // sim3 = q_l @ k^T   (M=256, N=8192)
    nt64_mma<<<dim3(2, 64, BH), 256, 69632>>>(pQL, pK, pSIM);
    softmaxN_kernel<<<BH * MM, 256>>>();
    // a3 @ v split-K partials (M=256, K=8192, 8 splits)
    nn64_mma<<<dim3(4, 8, BH), 128>>>(pSIM, pV, pPART, NSEQ,
        (size_t)MM * NSEQ, (size_t)NSEQ * 64, (size_t)8 * MM * 64, (size_t)MM * 64, 1024);
    a3vred_kernel<<<512, 256>>>();
    // W2 = Z @ a3v (M=256, K=256)
    nn64_mma<<<dim3(4, 1, BH), 128>>>(zc, pA3V, pW2, MM,
        (size_t)MM * MM, (size_t)MM * 64, (size_t)MM * 64, 0, MM);
    // sim1 = q @ k_l^T (M=8192, N=256) into g_sim
    nt64_mma<<<dim3(64, 2, BH), 256, 69632>>>(pQ, pKL, pSIM);
    softmax256_kernel<<<BH * NSEQ / 8, 256>>>();
    // out1 = a1 @ W2 (M=8192, K=256)
    nn64_mma<<<dim3(128, 1, BH), 128>>>(pSIM, pW2, pOUT1, MM,
        (size_t)NSEQ * MM, (size_t)MM * 64, (size_t)NSEQ * 64, 0, MM);
    conv_kernel<<<dim3(NSEQ / 128, BH), 256>>>(wres);
    outgemm_mma<<<dim3(TOK / 128, 4), 256, 71680>>>(x, wout, bout, out);
}